// round 1
// baseline (speedup 1.0000x reference)
#include <cuda_runtime.h>

#define BD 4
#define TD 2048
#define CD 512
#define HD 8
#define DD 64
#define BH 32                 // BD*HD
#define RWS 8192              // BD*TD
#define NRW 65536             // BD*TD*HD

// Scratch (device globals; no allocation at kernel_launch time)
__device__ float g_W[CD * CD];
__device__ float g_w[RWS * CD];
__device__ float g_q[RWS * CD];
__device__ float g_k[RWS * CD];
__device__ float g_v[RWS * CD];
__device__ float g_att[(size_t)BH * TD * TD];   // stores exp(att)
__device__ float g_prow[BH * TD];
__device__ float g_pcol[BH * TD];
__device__ float g_y[RWS * CD];

// ---------------------------------------------------------------- W = dw + qw
__global__ void k_addw(const float* __restrict__ dw, const float* __restrict__ qw) {
    int i = blockIdx.x * 256 + threadIdx.x;
    g_W[i] = dw[i] + qw[i];
}

// ---------------------------------------------------------------- g_w = x @ W^T
__global__ void k_wgemm(const float* __restrict__ x) {
    __shared__ float As[16][64], Bs[16][64];
    int tid = threadIdx.x, tx = tid & 15, ty = tid >> 4;
    const float* Ab = x   + (size_t)blockIdx.y * 64 * CD;
    const float* Bb = g_W + (size_t)blockIdx.x * 64 * CD;
    float* Cb = g_w + (size_t)blockIdx.y * 64 * CD + blockIdx.x * 64;
    float acc[4][4] = {};
    for (int k0 = 0; k0 < CD; k0 += 16) {
        #pragma unroll
        for (int l = 0; l < 4; l++) {
            int idx = tid + l * 256, r = idx >> 4, kk = idx & 15;
            As[kk][r] = Ab[(size_t)r * CD + k0 + kk];
            Bs[kk][r] = Bb[(size_t)r * CD + k0 + kk];
        }
        __syncthreads();
        #pragma unroll
        for (int kk = 0; kk < 16; kk++) {
            float a[4], b[4];
            #pragma unroll
            for (int u = 0; u < 4; u++) { a[u] = As[kk][ty * 4 + u]; b[u] = Bs[kk][tx * 4 + u]; }
            #pragma unroll
            for (int i = 0; i < 4; i++)
                #pragma unroll
                for (int j = 0; j < 4; j++)
                    acc[i][j] += a[i] * b[j];
        }
        __syncthreads();
    }
    #pragma unroll
    for (int i = 0; i < 4; i++)
        #pragma unroll
        for (int j = 0; j < 4; j++)
            Cb[(size_t)(ty * 4 + i) * CD + tx * 4 + j] = acc[i][j];
}

// ------------------------------------------- per-(b,t,h) rmsnorm -> q (w/ 1/sqrt(D)), k, v
__global__ void k_norm(const float* __restrict__ g1, const float* __restrict__ g2,
                       const float* __restrict__ g3) {
    int warp = (blockIdx.x * blockDim.x + threadIdx.x) >> 5;  // (b*T+t)*H + h
    int lane = threadIdx.x & 31;
    size_t off = (size_t)(warp >> 3) * CD + (warp & 7) * DD;
    float x0 = g_w[off + lane], x1 = g_w[off + lane + 32];
    float ss = x0 * x0 + x1 * x1;
    #pragma unroll
    for (int s = 16; s; s >>= 1) ss += __shfl_xor_sync(0xffffffffu, ss, s);
    float inv = rsqrtf(ss * (1.0f / 64.0f) + 1.1920929e-07f);
    float qs = inv * 0.125f;  // fold 1/sqrt(D)
    g_q[off + lane]      = x0 * qs  * g1[lane];
    g_q[off + lane + 32] = x1 * qs  * g1[lane + 32];
    g_k[off + lane]      = x0 * inv * g2[lane];
    g_k[off + lane + 32] = x1 * inv * g2[lane + 32];
    g_v[off + lane]      = x0 * inv * g3[lane];
    g_v[off + lane + 32] = x1 * inv * g3[lane + 32];
}

// ------------------------------------------- E = exp(q @ k^T) per (b,h) batch
__global__ void k_attgemm() {
    __shared__ float As[16][64], Bs[16][64];
    int bh = blockIdx.z;
    size_t hoff = (size_t)(bh >> 3) * TD * CD + (bh & 7) * DD;
    const float* Ab = g_q + hoff + (size_t)blockIdx.y * 64 * CD;
    const float* Bb = g_k + hoff + (size_t)blockIdx.x * 64 * CD;
    float* Cb = g_att + (size_t)bh * TD * TD + (size_t)blockIdx.y * 64 * TD + blockIdx.x * 64;
    int tid = threadIdx.x, tx = tid & 15, ty = tid >> 4;
    float acc[4][4] = {};
    for (int k0 = 0; k0 < DD; k0 += 16) {
        #pragma unroll
        for (int l = 0; l < 4; l++) {
            int idx = tid + l * 256, r = idx >> 4, kk = idx & 15;
            As[kk][r] = Ab[(size_t)r * CD + k0 + kk];
            Bs[kk][r] = Bb[(size_t)r * CD + k0 + kk];
        }
        __syncthreads();
        #pragma unroll
        for (int kk = 0; kk < 16; kk++) {
            float a[4], b[4];
            #pragma unroll
            for (int u = 0; u < 4; u++) { a[u] = As[kk][ty * 4 + u]; b[u] = Bs[kk][tx * 4 + u]; }
            #pragma unroll
            for (int i = 0; i < 4; i++)
                #pragma unroll
                for (int j = 0; j < 4; j++)
                    acc[i][j] += a[i] * b[j];
        }
        __syncthreads();
    }
    // |att| <= 8 (rmsnormed rows), so unshifted exp is safe in fp32
    #pragma unroll
    for (int i = 0; i < 4; i++)
        #pragma unroll
        for (int j = 0; j < 4; j++)
            Cb[(size_t)(ty * 4 + i) * TD + tx * 4 + j] = __expf(acc[i][j]);
}

// ------------------------------------------- p_row = 1 / rowsum(E)
__global__ void k_rowsum() {
    int row = blockIdx.x;  // bh*TD + i
    const float* a = g_att + (size_t)row * TD;
    float s = 0.f;
    for (int j = threadIdx.x; j < TD; j += 256) s += a[j];
    __shared__ float red[256];
    red[threadIdx.x] = s; __syncthreads();
    for (int st = 128; st; st >>= 1) {
        if (threadIdx.x < st) red[threadIdx.x] += red[threadIdx.x + st];
        __syncthreads();
    }
    if (threadIdx.x == 0) g_prow[row] = 1.0f / red[0];
}

// ------------------------------------------- p_col = 1 / colsum(E)
__global__ void k_colsum() {
    int bh = blockIdx.y;
    int j = blockIdx.x * 256 + threadIdx.x;
    const float* a = g_att + (size_t)bh * TD * TD + j;
    float s = 0.f;
    for (int i = 0; i < TD; i++) s += a[(size_t)i * TD];
    g_pcol[bh * TD + j] = 1.0f / s;
}

// ------------------------------------------- y = (E*(p_row_i + p_col_j)) @ v
__global__ void k_ygemm() {
    __shared__ float Ss[16][64], Vs[16][64];
    int bh = blockIdx.y;
    int i0 = blockIdx.x * 64;
    const float* e  = g_att  + (size_t)bh * TD * TD;
    const float* pr = g_prow + bh * TD;
    const float* pc = g_pcol + bh * TD;
    size_t hoff = (size_t)(bh >> 3) * TD * CD + (bh & 7) * DD;
    const float* v = g_v + hoff;
    float* y = g_y + hoff;
    int tid = threadIdx.x, tx = tid & 15, ty = tid >> 4;
    float acc[4][4] = {};
    for (int k0 = 0; k0 < TD; k0 += 16) {
        #pragma unroll
        for (int l = 0; l < 4; l++) {
            int idx = tid + l * 256, r = idx >> 4, kk = idx & 15;
            int gi = i0 + r, gj = k0 + kk;
            Ss[kk][r] = e[(size_t)gi * TD + gj] * (pr[gi] + pc[gj]);
        }
        #pragma unroll
        for (int l = 0; l < 4; l++) {
            int idx = tid + l * 256, d = idx & 63, kk = idx >> 6;
            Vs[kk][d] = v[(size_t)(k0 + kk) * CD + d];
        }
        __syncthreads();
        #pragma unroll
        for (int kk = 0; kk < 16; kk++) {
            float a[4], b[4];
            #pragma unroll
            for (int u = 0; u < 4; u++) { a[u] = Ss[kk][ty * 4 + u]; b[u] = Vs[kk][tx * 4 + u]; }
            #pragma unroll
            for (int i = 0; i < 4; i++)
                #pragma unroll
                for (int j = 0; j < 4; j++)
                    acc[i][j] += a[i] * b[j];
        }
        __syncthreads();
    }
    #pragma unroll
    for (int i = 0; i < 4; i++)
        #pragma unroll
        for (int j = 0; j < 4; j++)
            y[(size_t)(i0 + ty * 4 + i) * CD + tx * 4 + j] = acc[i][j];
}

// ------------------------------------------- out = y @ W  (NN)
__global__ void k_outgemm(float* __restrict__ out) {
    __shared__ float As[16][64], Bs[16][64];
    int tid = threadIdx.x, tx = tid & 15, ty = tid >> 4;
    const float* Ab = g_y + (size_t)blockIdx.y * 64 * CD;
    int j0 = blockIdx.x * 64;
    float* Cb = out + (size_t)blockIdx.y * 64 * CD + j0;
    float acc[4][4] = {};
    for (int k0 = 0; k0 < CD; k0 += 16) {
        #pragma unroll
        for (int l = 0; l < 4; l++) {
            int idx = tid + l * 256, r = idx >> 4, kk = idx & 15;
            As[kk][r] = Ab[(size_t)r * CD + k0 + kk];
        }
        #pragma unroll
        for (int l = 0; l < 4; l++) {
            int idx = tid + l * 256, j = idx & 63, kk = idx >> 6;
            Bs[kk][j] = g_W[(size_t)(k0 + kk) * CD + j0 + j];
        }
        __syncthreads();
        #pragma unroll
        for (int kk = 0; kk < 16; kk++) {
            float a[4], b[4];
            #pragma unroll
            for (int u = 0; u < 4; u++) { a[u] = As[kk][ty * 4 + u]; b[u] = Bs[kk][tx * 4 + u]; }
            #pragma unroll
            for (int i = 0; i < 4; i++)
                #pragma unroll
                for (int j = 0; j < 4; j++)
                    acc[i][j] += a[i] * b[j];
        }
        __syncthreads();
    }
    #pragma unroll
    for (int i = 0; i < 4; i++)
        #pragma unroll
        for (int j = 0; j < 4; j++)
            Cb[(size_t)(ty * 4 + i) * CD + tx * 4 + j] = acc[i][j];
}

extern "C" void kernel_launch(void* const* d_in, const int* in_sizes, int n_in,
                              void* d_out, int out_size) {
    (void)in_sizes; (void)n_in; (void)out_size;
    const float* x  = (const float*)d_in[0];
    const float* dw = (const float*)d_in[1];
    const float* qw = (const float*)d_in[2];
    const float* g1 = (const float*)d_in[3];
    const float* g2 = (const float*)d_in[4];
    const float* g3 = (const float*)d_in[5];
    float* out = (float*)d_out;

    k_addw<<<(CD * CD) / 256, 256>>>(dw, qw);
    k_wgemm<<<dim3(CD / 64, RWS / 64), 256>>>(x);
    k_norm<<<NRW / 8, 256>>>(g1, g2, g3);
    k_attgemm<<<dim3(TD / 64, TD / 64, BH), 256>>>();
    k_rowsum<<<BH * TD, 256>>>();
    k_colsum<<<dim3(TD / 256, BH), 256>>>();
    k_ygemm<<<dim3(TD / 64, BH), 256>>>();
    k_outgemm<<<dim3(CD / 64, RWS / 64), 256>>>(out);
}

// round 2
// speedup vs baseline: 1.8758x; 1.8758x over previous
#include <cuda_runtime.h>

#define TD 2048
#define CD 512
#define DD 64
#define BH 32
#define RWS 8192
#define NRW 65536

typedef unsigned long long u64;

// ---------------- scratch (device globals; no runtime allocation) ----------------
__device__ float g_W[CD * CD];
__device__ float g_w[RWS * CD];
__device__ float g_q[RWS * CD];
__device__ float g_k[RWS * CD];
__device__ float g_v[RWS * CD];
__device__ float g_att[(size_t)BH * TD * TD];   // exp(att)
__device__ float g_srow[BH * TD];
__device__ float g_scol[BH * TD];
__device__ float g_prow[BH * TD];
__device__ float g_pcol[BH * TD];
__device__ float g_y[RWS * CD];

// ---------------- packed fp32x2 helpers ----------------
__device__ __forceinline__ void fma2(u64& d, u64 a, u64 b) {
    asm("fma.rn.f32x2 %0, %1, %2, %0;" : "+l"(d) : "l"(a), "l"(b));
}
__device__ __forceinline__ float2 unpk(u64 v) {
    float2 f; asm("mov.b64 {%0, %1}, %2;" : "=f"(f.x), "=f"(f.y) : "l"(v)); return f;
}

// ---------------------------------------------------------------- W = dw + qw
__global__ void k_addw(const float* __restrict__ dw, const float* __restrict__ qw) {
    int i = blockIdx.x * 256 + threadIdx.x;
    g_W[i] = dw[i] + qw[i];
}

// ================================================================ g_w = x @ W^T
// 128x128 block, 8x8 microtile, K-stage 16, A dup'd in smem for f32x2.
__global__ __launch_bounds__(256, 2) void k_wgemm(const float* __restrict__ x) {
    __shared__ __align__(16) float sm[16 * 264 + 16 * 132];
    const int BO = 16 * 264;
    const int tid = threadIdx.x;
    const int tx = tid & 15, ty = tid >> 4;
    const int i0 = blockIdx.y * 128, j0 = blockIdx.x * 128;
    const float* Ab = x + (size_t)i0 * CD;
    const float* Bb = g_W + (size_t)j0 * CD;
    u64 acc[8][4] = {};
    #pragma unroll 1
    for (int s = 0; s < 32; s++) {
        int k0 = s * 16;
        #pragma unroll
        for (int l = 0; l < 2; l++) {
            int idx = tid + l * 256;
            int rr = idx >> 2, c4 = (idx & 3) * 4;
            float4 va = *(const float4*)(Ab + (size_t)rr * CD + k0 + c4);
            sm[(c4 + 0) * 264 + 2 * rr] = va.x; sm[(c4 + 0) * 264 + 2 * rr + 1] = va.x;
            sm[(c4 + 1) * 264 + 2 * rr] = va.y; sm[(c4 + 1) * 264 + 2 * rr + 1] = va.y;
            sm[(c4 + 2) * 264 + 2 * rr] = va.z; sm[(c4 + 2) * 264 + 2 * rr + 1] = va.z;
            sm[(c4 + 3) * 264 + 2 * rr] = va.w; sm[(c4 + 3) * 264 + 2 * rr + 1] = va.w;
            float4 vb = *(const float4*)(Bb + (size_t)rr * CD + k0 + c4);
            sm[BO + (c4 + 0) * 132 + rr] = vb.x;
            sm[BO + (c4 + 1) * 132 + rr] = vb.y;
            sm[BO + (c4 + 2) * 132 + rr] = vb.z;
            sm[BO + (c4 + 3) * 132 + rr] = vb.w;
        }
        __syncthreads();
        #pragma unroll
        for (int kk = 0; kk < 16; kk++) {
            u64 a[8], b[4]; ulonglong2 t;
            t = *(const ulonglong2*)&sm[kk * 264 + ty * 8];       a[0] = t.x; a[1] = t.y;
            t = *(const ulonglong2*)&sm[kk * 264 + ty * 8 + 4];   a[2] = t.x; a[3] = t.y;
            t = *(const ulonglong2*)&sm[kk * 264 + 128 + ty * 8]; a[4] = t.x; a[5] = t.y;
            t = *(const ulonglong2*)&sm[kk * 264 + 132 + ty * 8]; a[6] = t.x; a[7] = t.y;
            t = *(const ulonglong2*)&sm[BO + kk * 132 + tx * 4];      b[0] = t.x; b[1] = t.y;
            t = *(const ulonglong2*)&sm[BO + kk * 132 + 64 + tx * 4]; b[2] = t.x; b[3] = t.y;
            #pragma unroll
            for (int i = 0; i < 8; i++)
                #pragma unroll
                for (int j = 0; j < 4; j++)
                    fma2(acc[i][j], a[i], b[j]);
        }
        __syncthreads();
    }
    float* Cb = g_w + (size_t)i0 * CD + j0;
    #pragma unroll
    for (int i = 0; i < 8; i++) {
        int row = (i < 4) ? ty * 4 + i : 64 + ty * 4 + (i - 4);
        float2 p0 = unpk(acc[i][0]), p1 = unpk(acc[i][1]), p2 = unpk(acc[i][2]), p3 = unpk(acc[i][3]);
        *(float4*)(Cb + (size_t)row * CD + tx * 4)      = make_float4(p0.x, p0.y, p1.x, p1.y);
        *(float4*)(Cb + (size_t)row * CD + 64 + tx * 4) = make_float4(p2.x, p2.y, p3.x, p3.y);
    }
}

// ------------------------------------------- rmsnorm -> q (with 1/sqrt(D)), k, v
__global__ void k_norm(const float* __restrict__ g1, const float* __restrict__ g2,
                       const float* __restrict__ g3) {
    int warp = (blockIdx.x * blockDim.x + threadIdx.x) >> 5;
    int lane = threadIdx.x & 31;
    size_t off = (size_t)(warp >> 3) * CD + (warp & 7) * DD;
    float x0 = g_w[off + lane], x1 = g_w[off + lane + 32];
    float ss = x0 * x0 + x1 * x1;
    #pragma unroll
    for (int s = 16; s; s >>= 1) ss += __shfl_xor_sync(0xffffffffu, ss, s);
    float inv = rsqrtf(ss * (1.0f / 64.0f) + 1.1920929e-07f);
    float qs = inv * 0.125f;
    g_q[off + lane]      = x0 * qs  * g1[lane];
    g_q[off + lane + 32] = x1 * qs  * g1[lane + 32];
    g_k[off + lane]      = x0 * inv * g2[lane];
    g_k[off + lane + 32] = x1 * inv * g2[lane + 32];
    g_v[off + lane]      = x0 * inv * g3[lane];
    g_v[off + lane + 32] = x1 * inv * g3[lane + 32];
}

// ================================================================ E = exp(q@k^T) + fused row/col sums
__global__ __launch_bounds__(256, 2) void k_attgemm() {
    __shared__ __align__(16) float sm[16 * 264 + 16 * 132];
    const int BO = 16 * 264;
    const int tid = threadIdx.x;
    const int tx = tid & 15, ty = tid >> 4;
    const int bh = blockIdx.z;
    const int i0 = blockIdx.y * 128, j0 = blockIdx.x * 128;
    const size_t base = (size_t)(bh >> 3) * TD * CD + (bh & 7) * DD;
    const float* qb = g_q + base + (size_t)i0 * CD;
    const float* kb = g_k + base + (size_t)j0 * CD;
    u64 acc[8][4] = {};
    #pragma unroll 1
    for (int s = 0; s < 4; s++) {
        int k0 = s * 16;
        #pragma unroll
        for (int l = 0; l < 2; l++) {
            int idx = tid + l * 256;
            int rr = idx >> 2, c4 = (idx & 3) * 4;
            float4 va = *(const float4*)(qb + (size_t)rr * CD + k0 + c4);
            sm[(c4 + 0) * 264 + 2 * rr] = va.x; sm[(c4 + 0) * 264 + 2 * rr + 1] = va.x;
            sm[(c4 + 1) * 264 + 2 * rr] = va.y; sm[(c4 + 1) * 264 + 2 * rr + 1] = va.y;
            sm[(c4 + 2) * 264 + 2 * rr] = va.z; sm[(c4 + 2) * 264 + 2 * rr + 1] = va.z;
            sm[(c4 + 3) * 264 + 2 * rr] = va.w; sm[(c4 + 3) * 264 + 2 * rr + 1] = va.w;
            float4 vb = *(const float4*)(kb + (size_t)rr * CD + k0 + c4);
            sm[BO + (c4 + 0) * 132 + rr] = vb.x;
            sm[BO + (c4 + 1) * 132 + rr] = vb.y;
            sm[BO + (c4 + 2) * 132 + rr] = vb.z;
            sm[BO + (c4 + 3) * 132 + rr] = vb.w;
        }
        __syncthreads();
        #pragma unroll
        for (int kk = 0; kk < 16; kk++) {
            u64 a[8], b[4]; ulonglong2 t;
            t = *(const ulonglong2*)&sm[kk * 264 + ty * 8];       a[0] = t.x; a[1] = t.y;
            t = *(const ulonglong2*)&sm[kk * 264 + ty * 8 + 4];   a[2] = t.x; a[3] = t.y;
            t = *(const ulonglong2*)&sm[kk * 264 + 128 + ty * 8]; a[4] = t.x; a[5] = t.y;
            t = *(const ulonglong2*)&sm[kk * 264 + 132 + ty * 8]; a[6] = t.x; a[7] = t.y;
            t = *(const ulonglong2*)&sm[BO + kk * 132 + tx * 4];      b[0] = t.x; b[1] = t.y;
            t = *(const ulonglong2*)&sm[BO + kk * 132 + 64 + tx * 4]; b[2] = t.x; b[3] = t.y;
            #pragma unroll
            for (int i = 0; i < 8; i++)
                #pragma unroll
                for (int j = 0; j < 4; j++)
                    fma2(acc[i][j], a[i], b[j]);
        }
        __syncthreads();
    }
    // epilogue: exp (|att|<=8, unshifted exp safe), store E, fused partial sums
    float rs[8], cs[8] = {0, 0, 0, 0, 0, 0, 0, 0};
    float* ob = g_att + (size_t)bh * TD * TD + (size_t)i0 * TD + j0;
    #pragma unroll
    for (int i = 0; i < 8; i++) {
        int row = (i < 4) ? ty * 4 + i : 64 + ty * 4 + (i - 4);
        float2 p0 = unpk(acc[i][0]), p1 = unpk(acc[i][1]), p2 = unpk(acc[i][2]), p3 = unpk(acc[i][3]);
        float4 E0 = make_float4(__expf(p0.x), __expf(p0.y), __expf(p1.x), __expf(p1.y));
        float4 E1 = make_float4(__expf(p2.x), __expf(p2.y), __expf(p3.x), __expf(p3.y));
        *(float4*)(ob + (size_t)row * TD + tx * 4)      = E0;
        *(float4*)(ob + (size_t)row * TD + 64 + tx * 4) = E1;
        rs[i] = E0.x + E0.y + E0.z + E0.w + E1.x + E1.y + E1.z + E1.w;
        cs[0] += E0.x; cs[1] += E0.y; cs[2] += E0.z; cs[3] += E0.w;
        cs[4] += E1.x; cs[5] += E1.y; cs[6] += E1.z; cs[7] += E1.w;
    }
    float* rowp = sm;            // 16*132
    float* colp = sm + 16 * 132; // 16*132
    #pragma unroll
    for (int i = 0; i < 8; i++) {
        int row = (i < 4) ? ty * 4 + i : 64 + ty * 4 + (i - 4);
        rowp[tx * 132 + row] = rs[i];
    }
    #pragma unroll
    for (int j = 0; j < 8; j++) {
        int col = (j < 4) ? tx * 4 + j : 64 + tx * 4 + (j - 4);
        colp[ty * 132 + col] = cs[j];
    }
    __syncthreads();
    if (tid < 128) {
        float s = 0.f;
        #pragma unroll
        for (int t2 = 0; t2 < 16; t2++) s += rowp[t2 * 132 + tid];
        atomicAdd(&g_srow[bh * TD + i0 + tid], s);
    } else {
        int col = tid - 128;
        float s = 0.f;
        #pragma unroll
        for (int t2 = 0; t2 < 16; t2++) s += colp[t2 * 132 + col];
        atomicAdd(&g_scol[bh * TD + j0 + col], s);
    }
}

// ------------------------------------------- reciprocals of sums
__global__ void k_recip() {
    int i = blockIdx.x * 256 + threadIdx.x;
    g_prow[i] = 1.0f / g_srow[i];
    g_pcol[i] = 1.0f / g_scol[i];
}

// ================================================================ y = (E*(pr_i+pc_j)) @ v
// 256x64 block, 8x8 microtile (tx 0..7), K-stage 16.
__global__ __launch_bounds__(256, 2) void k_ygemm() {
    __shared__ __align__(16) float sm[16 * 520 + 16 * 68];
    const int VO = 16 * 520;
    const int tid = threadIdx.x;
    const int tx = tid & 7, ty = tid >> 3;
    const int bh = blockIdx.y;
    const int i0 = blockIdx.x * 256;
    const float* eb  = g_att + (size_t)bh * TD * TD;
    const float* prb = g_prow + bh * TD;
    const float* pcb = g_pcol + bh * TD;
    const size_t base = (size_t)(bh >> 3) * TD * CD + (bh & 7) * DD;
    const float* vb = g_v + base;
    u64 acc[8][4] = {};
    float prv[4]; const float* erow[4];
    #pragma unroll
    for (int l = 0; l < 4; l++) {
        int idx = tid + l * 256; int rr = idx >> 2;
        prv[l] = prb[i0 + rr];
        erow[l] = eb + (size_t)(i0 + rr) * TD;
    }
    #pragma unroll 1
    for (int s = 0; s < 128; s++) {
        int k0 = s * 16;
        #pragma unroll
        for (int l = 0; l < 4; l++) {
            int idx = tid + l * 256;
            int rr = idx >> 2, c4 = (idx & 3) * 4;
            float4 ev = *(const float4*)(erow[l] + k0 + c4);
            float4 pv = *(const float4*)(pcb + k0 + c4);
            float p = prv[l];
            float s0 = ev.x * (p + pv.x), s1 = ev.y * (p + pv.y);
            float s2 = ev.z * (p + pv.z), s3 = ev.w * (p + pv.w);
            sm[(c4 + 0) * 520 + 2 * rr] = s0; sm[(c4 + 0) * 520 + 2 * rr + 1] = s0;
            sm[(c4 + 1) * 520 + 2 * rr] = s1; sm[(c4 + 1) * 520 + 2 * rr + 1] = s1;
            sm[(c4 + 2) * 520 + 2 * rr] = s2; sm[(c4 + 2) * 520 + 2 * rr + 1] = s2;
            sm[(c4 + 3) * 520 + 2 * rr] = s3; sm[(c4 + 3) * 520 + 2 * rr + 1] = s3;
        }
        {
            int kk = tid >> 4, d4 = (tid & 15) * 4;
            *(float4*)&sm[VO + kk * 68 + d4] = *(const float4*)(vb + (size_t)(k0 + kk) * CD + d4);
        }
        __syncthreads();
        #pragma unroll
        for (int kk = 0; kk < 16; kk++) {
            u64 a[8], b[4]; ulonglong2 t;
            t = *(const ulonglong2*)&sm[kk * 520 + ty * 8];       a[0] = t.x; a[1] = t.y;
            t = *(const ulonglong2*)&sm[kk * 520 + ty * 8 + 4];   a[2] = t.x; a[3] = t.y;
            t = *(const ulonglong2*)&sm[kk * 520 + 256 + ty * 8]; a[4] = t.x; a[5] = t.y;
            t = *(const ulonglong2*)&sm[kk * 520 + 260 + ty * 8]; a[6] = t.x; a[7] = t.y;
            t = *(const ulonglong2*)&sm[VO + kk * 68 + tx * 4];      b[0] = t.x; b[1] = t.y;
            t = *(const ulonglong2*)&sm[VO + kk * 68 + 32 + tx * 4]; b[2] = t.x; b[3] = t.y;
            #pragma unroll
            for (int i = 0; i < 8; i++)
                #pragma unroll
                for (int j = 0; j < 4; j++)
                    fma2(acc[i][j], a[i], b[j]);
        }
        __syncthreads();
    }
    float* yb = g_y + base + (size_t)i0 * CD;
    #pragma unroll
    for (int i = 0; i < 8; i++) {
        int row = (i < 4) ? ty * 4 + i : 128 + ty * 4 + (i - 4);
        float2 p0 = unpk(acc[i][0]), p1 = unpk(acc[i][1]), p2 = unpk(acc[i][2]), p3 = unpk(acc[i][3]);
        *(float4*)(yb + (size_t)row * CD + tx * 4)      = make_float4(p0.x, p0.y, p1.x, p1.y);
        *(float4*)(yb + (size_t)row * CD + 32 + tx * 4) = make_float4(p2.x, p2.y, p3.x, p3.y);
    }
}

// ================================================================ out = y @ W (NN)
__global__ __launch_bounds__(256, 2) void k_outgemm(float* __restrict__ out) {
    __shared__ __align__(16) float sm[16 * 264 + 16 * 132];
    const int BO = 16 * 264;
    const int tid = threadIdx.x;
    const int tx = tid & 15, ty = tid >> 4;
    const int i0 = blockIdx.y * 128, j0 = blockIdx.x * 128;
    const float* Ab = g_y + (size_t)i0 * CD;
    u64 acc[8][4] = {};
    #pragma unroll 1
    for (int s = 0; s < 32; s++) {
        int k0 = s * 16;
        #pragma unroll
        for (int l = 0; l < 2; l++) {
            int idx = tid + l * 256;
            int rr = idx >> 2, c4 = (idx & 3) * 4;
            float4 va = *(const float4*)(Ab + (size_t)rr * CD + k0 + c4);
            sm[(c4 + 0) * 264 + 2 * rr] = va.x; sm[(c4 + 0) * 264 + 2 * rr + 1] = va.x;
            sm[(c4 + 1) * 264 + 2 * rr] = va.y; sm[(c4 + 1) * 264 + 2 * rr + 1] = va.y;
            sm[(c4 + 2) * 264 + 2 * rr] = va.z; sm[(c4 + 2) * 264 + 2 * rr + 1] = va.z;
            sm[(c4 + 3) * 264 + 2 * rr] = va.w; sm[(c4 + 3) * 264 + 2 * rr + 1] = va.w;
            // B direct (k-major): W[k0+kk][j0 + j]
            int kk = idx >> 5, j4 = (idx & 31) * 4;
            *(float4*)&sm[BO + kk * 132 + j4] =
                *(const float4*)(g_W + (size_t)(k0 + kk) * CD + j0 + j4);
        }
        __syncthreads();
        #pragma unroll
        for (int kk = 0; kk < 16; kk++) {
            u64 a[8], b[4]; ulonglong2 t;
            t = *(const ulonglong2*)&sm[kk * 264 + ty * 8];       a[0] = t.x; a[1] = t.y;
            t = *(const ulonglong2*)&sm[kk * 264 + ty * 8 + 4];   a[2] = t.x; a[3] = t.y;
            t = *(const ulonglong2*)&sm[kk * 264 + 128 + ty * 8]; a[4] = t.x; a[5] = t.y;
            t = *(const ulonglong2*)&sm[kk * 264 + 132 + ty * 8]; a[6] = t.x; a[7] = t.y;
            t = *(const ulonglong2*)&sm[BO + kk * 132 + tx * 4];      b[0] = t.x; b[1] = t.y;
            t = *(const ulonglong2*)&sm[BO + kk * 132 + 64 + tx * 4]; b[2] = t.x; b[3] = t.y;
            #pragma unroll
            for (int i = 0; i < 8; i++)
                #pragma unroll
                for (int j = 0; j < 4; j++)
                    fma2(acc[i][j], a[i], b[j]);
        }
        __syncthreads();
    }
    float* Cb = out + (size_t)i0 * CD + j0;
    #pragma unroll
    for (int i = 0; i < 8; i++) {
        int row = (i < 4) ? ty * 4 + i : 64 + ty * 4 + (i - 4);
        float2 p0 = unpk(acc[i][0]), p1 = unpk(acc[i][1]), p2 = unpk(acc[i][2]), p3 = unpk(acc[i][3]);
        *(float4*)(Cb + (size_t)row * CD + tx * 4)      = make_float4(p0.x, p0.y, p1.x, p1.y);
        *(float4*)(Cb + (size_t)row * CD + 64 + tx * 4) = make_float4(p2.x, p2.y, p3.x, p3.y);
    }
}

extern "C" void kernel_launch(void* const* d_in, const int* in_sizes, int n_in,
                              void* d_out, int out_size) {
    (void)in_sizes; (void)n_in; (void)out_size;
    const float* x  = (const float*)d_in[0];
    const float* dw = (const float*)d_in[1];
    const float* qw = (const float*)d_in[2];
    const float* g1 = (const float*)d_in[3];
    const float* g2 = (const float*)d_in[4];
    const float* g3 = (const float*)d_in[5];
    float* out = (float*)d_out;

    float *ps, *pc;
    cudaGetSymbolAddress((void**)&ps, g_srow);
    cudaGetSymbolAddress((void**)&pc, g_scol);
    cudaMemsetAsync(ps, 0, BH * TD * sizeof(float));
    cudaMemsetAsync(pc, 0, BH * TD * sizeof(float));

    k_addw<<<(CD * CD) / 256, 256>>>(dw, qw);
    k_wgemm<<<dim3(CD / 128, RWS / 128), 256>>>(x);
    k_norm<<<NRW / 8, 256>>>(g1, g2, g3);
    k_attgemm<<<dim3(TD / 128, TD / 128, BH), 256>>>();
    k_recip<<<(BH * TD) / 256, 256>>>();
    k_ygemm<<<dim3(TD / 256, BH), 256>>>();
    k_outgemm<<<dim3(CD / 128, RWS / 128), 256>>>(out);
}

// round 3
// speedup vs baseline: 2.9665x; 1.5814x over previous
#include <cuda_runtime.h>

#define TD 2048
#define CD 512
#define DD 64
#define BH 32
#define RWS 8192
#define NRW 65536

typedef unsigned long long u64;
typedef unsigned int u32;

// ---------------- scratch ----------------
__device__ float g_W[CD * CD];
__device__ float g_w[RWS * CD];
__device__ float g_q[RWS * CD];
__device__ float g_k[RWS * CD];
__device__ float g_v[RWS * CD];
__device__ float g_att[(size_t)BH * TD * TD];   // exp(att)
__device__ float g_srow[BH * TD];
__device__ float g_scol[BH * TD];
__device__ float g_prow[BH * TD];
__device__ float g_pcol[BH * TD];
__device__ float g_y[RWS * CD];

// ---------------- helpers ----------------
__device__ __forceinline__ void fma2(u64& d, u64 a, u64 b) {
    asm("fma.rn.f32x2 %0, %1, %2, %0;" : "+l"(d) : "l"(a), "l"(b));
}
__device__ __forceinline__ float2 unpk(u64 v) {
    float2 f; asm("mov.b64 {%0, %1}, %2;" : "=f"(f.x), "=f"(f.y) : "l"(v)); return f;
}
__device__ __forceinline__ u32 tf32c(float f) {
    u32 r; asm("cvt.rna.tf32.f32 %0, %1;" : "=r"(r) : "f"(f)); return r;
}
// D(16x8) += A(16x8,row) * B(8x8,col)   tf32
__device__ __forceinline__ void mma8(float* d, const u32* a, const u32* b) {
    asm("mma.sync.aligned.m16n8k8.row.col.f32.tf32.tf32.f32 "
        "{%0,%1,%2,%3},{%4,%5,%6,%7},{%8,%9},{%0,%1,%2,%3};"
        : "+f"(d[0]), "+f"(d[1]), "+f"(d[2]), "+f"(d[3])
        : "r"(a[0]), "r"(a[1]), "r"(a[2]), "r"(a[3]), "r"(b[0]), "r"(b[1]));
}

// ---------------------------------------------------------------- W = dw + qw
__global__ void k_addw(const float* __restrict__ dw, const float* __restrict__ qw) {
    int i = blockIdx.x * 256 + threadIdx.x;
    g_W[i] = dw[i] + qw[i];
}

// ================================================================ g_w = x @ W^T (FFMA2, exact)
__global__ __launch_bounds__(256, 2) void k_wgemm(const float* __restrict__ x) {
    __shared__ __align__(16) float sm[16 * 264 + 16 * 132];
    const int BO = 16 * 264;
    const int tid = threadIdx.x;
    const int tx = tid & 15, ty = tid >> 4;
    const int i0 = blockIdx.y * 128, j0 = blockIdx.x * 128;
    const float* Ab = x + (size_t)i0 * CD;
    const float* Bb = g_W + (size_t)j0 * CD;
    u64 acc[8][4] = {};
    #pragma unroll 1
    for (int s = 0; s < 32; s++) {
        int k0 = s * 16;
        #pragma unroll
        for (int l = 0; l < 2; l++) {
            int idx = tid + l * 256;
            int rr = idx >> 2, c4 = (idx & 3) * 4;
            float4 va = *(const float4*)(Ab + (size_t)rr * CD + k0 + c4);
            sm[(c4 + 0) * 264 + 2 * rr] = va.x; sm[(c4 + 0) * 264 + 2 * rr + 1] = va.x;
            sm[(c4 + 1) * 264 + 2 * rr] = va.y; sm[(c4 + 1) * 264 + 2 * rr + 1] = va.y;
            sm[(c4 + 2) * 264 + 2 * rr] = va.z; sm[(c4 + 2) * 264 + 2 * rr + 1] = va.z;
            sm[(c4 + 3) * 264 + 2 * rr] = va.w; sm[(c4 + 3) * 264 + 2 * rr + 1] = va.w;
            float4 vb = *(const float4*)(Bb + (size_t)rr * CD + k0 + c4);
            sm[BO + (c4 + 0) * 132 + rr] = vb.x;
            sm[BO + (c4 + 1) * 132 + rr] = vb.y;
            sm[BO + (c4 + 2) * 132 + rr] = vb.z;
            sm[BO + (c4 + 3) * 132 + rr] = vb.w;
        }
        __syncthreads();
        #pragma unroll
        for (int kk = 0; kk < 16; kk++) {
            u64 a[8], b[4]; ulonglong2 t;
            t = *(const ulonglong2*)&sm[kk * 264 + ty * 8];       a[0] = t.x; a[1] = t.y;
            t = *(const ulonglong2*)&sm[kk * 264 + ty * 8 + 4];   a[2] = t.x; a[3] = t.y;
            t = *(const ulonglong2*)&sm[kk * 264 + 128 + ty * 8]; a[4] = t.x; a[5] = t.y;
            t = *(const ulonglong2*)&sm[kk * 264 + 132 + ty * 8]; a[6] = t.x; a[7] = t.y;
            t = *(const ulonglong2*)&sm[BO + kk * 132 + tx * 4];      b[0] = t.x; b[1] = t.y;
            t = *(const ulonglong2*)&sm[BO + kk * 132 + 64 + tx * 4]; b[2] = t.x; b[3] = t.y;
            #pragma unroll
            for (int i = 0; i < 8; i++)
                #pragma unroll
                for (int j = 0; j < 4; j++)
                    fma2(acc[i][j], a[i], b[j]);
        }
        __syncthreads();
    }
    float* Cb = g_w + (size_t)i0 * CD + j0;
    #pragma unroll
    for (int i = 0; i < 8; i++) {
        int row = (i < 4) ? ty * 4 + i : 64 + ty * 4 + (i - 4);
        float2 p0 = unpk(acc[i][0]), p1 = unpk(acc[i][1]), p2 = unpk(acc[i][2]), p3 = unpk(acc[i][3]);
        *(float4*)(Cb + (size_t)row * CD + tx * 4)      = make_float4(p0.x, p0.y, p1.x, p1.y);
        *(float4*)(Cb + (size_t)row * CD + 64 + tx * 4) = make_float4(p2.x, p2.y, p3.x, p3.y);
    }
}

// ------------------------------------------- rmsnorm -> q (with 1/sqrt(D)), k, v
__global__ void k_norm(const float* __restrict__ g1, const float* __restrict__ g2,
                       const float* __restrict__ g3) {
    int warp = (blockIdx.x * blockDim.x + threadIdx.x) >> 5;
    int lane = threadIdx.x & 31;
    size_t off = (size_t)(warp >> 3) * CD + (warp & 7) * DD;
    float x0 = g_w[off + lane], x1 = g_w[off + lane + 32];
    float ss = x0 * x0 + x1 * x1;
    #pragma unroll
    for (int s = 16; s; s >>= 1) ss += __shfl_xor_sync(0xffffffffu, ss, s);
    float inv = rsqrtf(ss * (1.0f / 64.0f) + 1.1920929e-07f);
    float qs = inv * 0.125f;
    g_q[off + lane]      = x0 * qs  * g1[lane];
    g_q[off + lane + 32] = x1 * qs  * g1[lane + 32];
    g_k[off + lane]      = x0 * inv * g2[lane];
    g_k[off + lane + 32] = x1 * inv * g2[lane + 32];
    g_v[off + lane]      = x0 * inv * g3[lane];
    g_v[off + lane + 32] = x1 * inv * g3[lane + 32];
}

// ================================================================ E = exp(q@k^T) via tf32 MMA
// 128x128 tile, 8 warps (4m x 2n). smem: K-perm layout [0,4,1,5,2,6,3,7] per 8-chunk,
// so each fragment is one LDS.64. 2 K-stages of 32.
__global__ __launch_bounds__(256, 1) void k_attgemm() {
    __shared__ __align__(16) float sq[128 * 40];
    __shared__ __align__(16) float sk[128 * 40];
    const int tid = threadIdx.x;
    const int lane = tid & 31, warp = tid >> 5;
    const int wm = warp >> 1, wn = warp & 1;
    const int g = lane >> 2, t = lane & 3;
    const int bh = blockIdx.z;
    const int i0 = blockIdx.y * 128, j0 = blockIdx.x * 128;
    const size_t base = (size_t)(bh >> 3) * TD * CD + (bh & 7) * DD;
    const float* qb = g_q + base + (size_t)i0 * CD;
    const float* kb = g_k + base + (size_t)j0 * CD;
    float d[2][8][4] = {};
    #pragma unroll
    for (int stage = 0; stage < 2; stage++) {
        int k0 = stage * 32;
        #pragma unroll
        for (int l = 0; l < 4; l++) {
            int idx = tid + l * 256;
            int rr = idx >> 3, c4 = (idx & 7) * 4;
            int pbase = (c4 & 24) + ((c4 & 4) ? 1 : 0);
            float4 v = *(const float4*)(qb + (size_t)rr * CD + k0 + c4);
            u32* dq = (u32*)&sq[rr * 40 + pbase];
            dq[0] = tf32c(v.x); dq[2] = tf32c(v.y); dq[4] = tf32c(v.z); dq[6] = tf32c(v.w);
            float4 w = *(const float4*)(kb + (size_t)rr * CD + k0 + c4);
            u32* dk = (u32*)&sk[rr * 40 + pbase];
            dk[0] = tf32c(w.x); dk[2] = tf32c(w.y); dk[4] = tf32c(w.z); dk[6] = tf32c(w.w);
        }
        __syncthreads();
        #pragma unroll
        for (int ks = 0; ks < 4; ks++) {
            u32 a[2][4], b[8][2];
            #pragma unroll
            for (int mt = 0; mt < 2; mt++) {
                float2 lo = *(const float2*)&sq[(wm * 32 + mt * 16 + g) * 40 + ks * 8 + 2 * t];
                float2 hi = *(const float2*)&sq[(wm * 32 + mt * 16 + g + 8) * 40 + ks * 8 + 2 * t];
                a[mt][0] = __float_as_uint(lo.x); a[mt][2] = __float_as_uint(lo.y);
                a[mt][1] = __float_as_uint(hi.x); a[mt][3] = __float_as_uint(hi.y);
            }
            #pragma unroll
            for (int nt = 0; nt < 8; nt++) {
                float2 bb = *(const float2*)&sk[(wn * 64 + nt * 8 + g) * 40 + ks * 8 + 2 * t];
                b[nt][0] = __float_as_uint(bb.x); b[nt][1] = __float_as_uint(bb.y);
            }
            #pragma unroll
            for (int mt = 0; mt < 2; mt++)
                #pragma unroll
                for (int nt = 0; nt < 8; nt++)
                    mma8(d[mt][nt], a[mt], b[nt]);
        }
        __syncthreads();
    }
    // epilogue: exp (|att|<=8), store E, fused row/col partial sums
    float* ob = g_att + (size_t)bh * TD * TD + (size_t)(i0) * TD + j0;
    float csum0[8], csum1[8];
    #pragma unroll
    for (int nt = 0; nt < 8; nt++) { csum0[nt] = 0.f; csum1[nt] = 0.f; }
    float rsum[2][2];
    #pragma unroll
    for (int mt = 0; mt < 2; mt++) {
        rsum[mt][0] = 0.f; rsum[mt][1] = 0.f;
        int row0 = wm * 32 + mt * 16 + g;
        #pragma unroll
        for (int nt = 0; nt < 8; nt++) {
            float e0 = __expf(d[mt][nt][0]), e1 = __expf(d[mt][nt][1]);
            float e2 = __expf(d[mt][nt][2]), e3 = __expf(d[mt][nt][3]);
            int col = wn * 64 + nt * 8 + 2 * t;
            *(float2*)(ob + (size_t)row0 * TD + col)       = make_float2(e0, e1);
            *(float2*)(ob + (size_t)(row0 + 8) * TD + col) = make_float2(e2, e3);
            rsum[mt][0] += e0 + e1; rsum[mt][1] += e2 + e3;
            csum0[nt] += e0 + e2;  csum1[nt] += e1 + e3;
        }
    }
    // row reduce over t (4 lanes in group)
    #pragma unroll
    for (int mt = 0; mt < 2; mt++)
        #pragma unroll
        for (int h = 0; h < 2; h++) {
            rsum[mt][h] += __shfl_xor_sync(0xffffffffu, rsum[mt][h], 1);
            rsum[mt][h] += __shfl_xor_sync(0xffffffffu, rsum[mt][h], 2);
        }
    // col reduce over g (8 groups)
    #pragma unroll
    for (int nt = 0; nt < 8; nt++) {
        csum0[nt] += __shfl_xor_sync(0xffffffffu, csum0[nt], 4);
        csum0[nt] += __shfl_xor_sync(0xffffffffu, csum0[nt], 8);
        csum0[nt] += __shfl_xor_sync(0xffffffffu, csum0[nt], 16);
        csum1[nt] += __shfl_xor_sync(0xffffffffu, csum1[nt], 4);
        csum1[nt] += __shfl_xor_sync(0xffffffffu, csum1[nt], 8);
        csum1[nt] += __shfl_xor_sync(0xffffffffu, csum1[nt], 16);
    }
    float* srowp = sq;        // [2][128]
    float* scolp = sq + 256;  // [4][128]
    if (t == 0) {
        #pragma unroll
        for (int mt = 0; mt < 2; mt++) {
            srowp[wn * 128 + wm * 32 + mt * 16 + g]     = rsum[mt][0];
            srowp[wn * 128 + wm * 32 + mt * 16 + g + 8] = rsum[mt][1];
        }
    }
    if (g == 0) {
        #pragma unroll
        for (int nt = 0; nt < 8; nt++) {
            scolp[wm * 128 + wn * 64 + nt * 8 + 2 * t]     = csum0[nt];
            scolp[wm * 128 + wn * 64 + nt * 8 + 2 * t + 1] = csum1[nt];
        }
    }
    __syncthreads();
    if (tid < 128) {
        atomicAdd(&g_srow[bh * TD + i0 + tid], srowp[tid] + srowp[128 + tid]);
    } else {
        int c = tid - 128;
        atomicAdd(&g_scol[bh * TD + j0 + c],
                  scolp[c] + scolp[128 + c] + scolp[256 + c] + scolp[384 + c]);
    }
}

// ------------------------------------------- reciprocals of sums
__global__ void k_recip() {
    int i = blockIdx.x * 256 + threadIdx.x;
    g_prow[i] = 1.0f / g_srow[i];
    g_pcol[i] = 1.0f / g_scol[i];
}

// ================================================================ y = (E*(pr+pc)) @ v via tf32 MMA
// 128x64 tile, 8 warps (4m x 2n), K-chunks of 32.
__global__ __launch_bounds__(256, 2) void k_ygemm() {
    __shared__ __align__(16) float sS[128 * 40];
    __shared__ __align__(16) float sV[32 * 72];
    __shared__ float spr[128];
    const int tid = threadIdx.x;
    const int lane = tid & 31, warp = tid >> 5;
    const int wm = warp >> 1, wn = warp & 1;
    const int g = lane >> 2, t = lane & 3;
    const int bh = blockIdx.y;
    const int i0 = blockIdx.x * 128;
    const float* eb  = g_att + (size_t)bh * TD * TD + (size_t)i0 * TD;
    const float* pcb = g_pcol + bh * TD;
    const size_t base = (size_t)(bh >> 3) * TD * CD + (bh & 7) * DD;
    const float* vb = g_v + base;
    if (tid < 128) spr[tid] = g_prow[bh * TD + i0 + tid];
    __syncthreads();
    float d[2][4][4] = {};
    #pragma unroll 1
    for (int kc = 0; kc < 64; kc++) {
        int k0 = kc * 32;
        #pragma unroll
        for (int l = 0; l < 4; l++) {
            int idx = tid + l * 256;
            int rr = idx >> 3, c4 = (idx & 7) * 4;
            int pbase = (c4 & 24) + ((c4 & 4) ? 1 : 0);
            float4 ev = *(const float4*)(eb + (size_t)rr * TD + k0 + c4);
            float4 pv = *(const float4*)(pcb + k0 + c4);
            float p = spr[rr];
            u32* ds = (u32*)&sS[rr * 40 + pbase];
            ds[0] = tf32c(ev.x * (p + pv.x)); ds[2] = tf32c(ev.y * (p + pv.y));
            ds[4] = tf32c(ev.z * (p + pv.z)); ds[6] = tf32c(ev.w * (p + pv.w));
        }
        #pragma unroll
        for (int l = 0; l < 2; l++) {
            int idx = tid + l * 256;
            int rk = idx >> 4, n4 = (idx & 15) * 4;
            float4 vv = *(const float4*)(vb + (size_t)(k0 + rk) * CD + n4);
            u32* dv = (u32*)&sV[rk * 72 + n4];
            dv[0] = tf32c(vv.x); dv[1] = tf32c(vv.y); dv[2] = tf32c(vv.z); dv[3] = tf32c(vv.w);
        }
        __syncthreads();
        #pragma unroll
        for (int ks = 0; ks < 4; ks++) {
            u32 a[2][4], b[4][2];
            #pragma unroll
            for (int mt = 0; mt < 2; mt++) {
                float2 lo = *(const float2*)&sS[(wm * 32 + mt * 16 + g) * 40 + ks * 8 + 2 * t];
                float2 hi = *(const float2*)&sS[(wm * 32 + mt * 16 + g + 8) * 40 + ks * 8 + 2 * t];
                a[mt][0] = __float_as_uint(lo.x); a[mt][2] = __float_as_uint(lo.y);
                a[mt][1] = __float_as_uint(hi.x); a[mt][3] = __float_as_uint(hi.y);
            }
            #pragma unroll
            for (int nt = 0; nt < 4; nt++) {
                int n = wn * 32 + nt * 8 + g;
                b[nt][0] = __float_as_uint(sV[(ks * 8 + t) * 72 + n]);
                b[nt][1] = __float_as_uint(sV[(ks * 8 + t + 4) * 72 + n]);
            }
            #pragma unroll
            for (int mt = 0; mt < 2; mt++)
                #pragma unroll
                for (int nt = 0; nt < 4; nt++)
                    mma8(d[mt][nt], a[mt], b[nt]);
        }
        __syncthreads();
    }
    float* yb = g_y + base + (size_t)i0 * CD;
    #pragma unroll
    for (int mt = 0; mt < 2; mt++) {
        int row0 = wm * 32 + mt * 16 + g;
        #pragma unroll
        for (int nt = 0; nt < 4; nt++) {
            int col = wn * 32 + nt * 8 + 2 * t;
            *(float2*)(yb + (size_t)row0 * CD + col)       = make_float2(d[mt][nt][0], d[mt][nt][1]);
            *(float2*)(yb + (size_t)(row0 + 8) * CD + col) = make_float2(d[mt][nt][2], d[mt][nt][3]);
        }
    }
}

// ================================================================ out = y @ W (NN, FFMA2, exact)
__global__ __launch_bounds__(256, 2) void k_outgemm(float* __restrict__ out) {
    __shared__ __align__(16) float sm[16 * 264 + 16 * 132];
    const int BO = 16 * 264;
    const int tid = threadIdx.x;
    const int tx = tid & 15, ty = tid >> 4;
    const int i0 = blockIdx.y * 128, j0 = blockIdx.x * 128;
    const float* Ab = g_y + (size_t)i0 * CD;
    u64 acc[8][4] = {};
    #pragma unroll 1
    for (int s = 0; s < 32; s++) {
        int k0 = s * 16;
        #pragma unroll
        for (int l = 0; l < 2; l++) {
            int idx = tid + l * 256;
            int rr = idx >> 2, c4 = (idx & 3) * 4;
            float4 va = *(const float4*)(Ab + (size_t)rr * CD + k0 + c4);
            sm[(c4 + 0) * 264 + 2 * rr] = va.x; sm[(c4 + 0) * 264 + 2 * rr + 1] = va.x;
            sm[(c4 + 1) * 264 + 2 * rr] = va.y; sm[(c4 + 1) * 264 + 2 * rr + 1] = va.y;
            sm[(c4 + 2) * 264 + 2 * rr] = va.z; sm[(c4 + 2) * 264 + 2 * rr + 1] = va.z;
            sm[(c4 + 3) * 264 + 2 * rr] = va.w; sm[(c4 + 3) * 264 + 2 * rr + 1] = va.w;
            int kk = idx >> 5, j4 = (idx & 31) * 4;
            *(float4*)&sm[BO + kk * 132 + j4] =
                *(const float4*)(g_W + (size_t)(k0 + kk) * CD + j0 + j4);
        }
        __syncthreads();
        #pragma unroll
        for (int kk = 0; kk < 16; kk++) {
            u64 a[8], b[4]; ulonglong2 t;
            t = *(const ulonglong2*)&sm[kk * 264 + ty * 8];       a[0] = t.x; a[1] = t.y;
            t = *(const ulonglong2*)&sm[kk * 264 + ty * 8 + 4];   a[2] = t.x; a[3] = t.y;
            t = *(const ulonglong2*)&sm[kk * 264 + 128 + ty * 8]; a[4] = t.x; a[5] = t.y;
            t = *(const ulonglong2*)&sm[kk * 264 + 132 + ty * 8]; a[6] = t.x; a[7] = t.y;
            t = *(const ulonglong2*)&sm[BO + kk * 132 + tx * 4];      b[0] = t.x; b[1] = t.y;
            t = *(const ulonglong2*)&sm[BO + kk * 132 + 64 + tx * 4]; b[2] = t.x; b[3] = t.y;
            #pragma unroll
            for (int i = 0; i < 8; i++)
                #pragma unroll
                for (int j = 0; j < 4; j++)
                    fma2(acc[i][j], a[i], b[j]);
        }
        __syncthreads();
    }
    float* Cb = out + (size_t)i0 * CD + j0;
    #pragma unroll
    for (int i = 0; i < 8; i++) {
        int row = (i < 4) ? ty * 4 + i : 64 + ty * 4 + (i - 4);
        float2 p0 = unpk(acc[i][0]), p1 = unpk(acc[i][1]), p2 = unpk(acc[i][2]), p3 = unpk(acc[i][3]);
        *(float4*)(Cb + (size_t)row * CD + tx * 4)      = make_float4(p0.x, p0.y, p1.x, p1.y);
        *(float4*)(Cb + (size_t)row * CD + 64 + tx * 4) = make_float4(p2.x, p2.y, p3.x, p3.y);
    }
}

extern "C" void kernel_launch(void* const* d_in, const int* in_sizes, int n_in,
                              void* d_out, int out_size) {
    (void)in_sizes; (void)n_in; (void)out_size;
    const float* x  = (const float*)d_in[0];
    const float* dw = (const float*)d_in[1];
    const float* qw = (const float*)d_in[2];
    const float* g1 = (const float*)d_in[3];
    const float* g2 = (const float*)d_in[4];
    const float* g3 = (const float*)d_in[5];
    float* out = (float*)d_out;

    float *ps, *pc;
    cudaGetSymbolAddress((void**)&ps, g_srow);
    cudaGetSymbolAddress((void**)&pc, g_scol);
    cudaMemsetAsync(ps, 0, BH * TD * sizeof(float));
    cudaMemsetAsync(pc, 0, BH * TD * sizeof(float));

    k_addw<<<(CD * CD) / 256, 256>>>(dw, qw);
    k_wgemm<<<dim3(CD / 128, RWS / 128), 256>>>(x);
    k_norm<<<NRW / 8, 256>>>(g1, g2, g3);
    k_attgemm<<<dim3(TD / 128, TD / 128, BH), 256>>>();
    k_recip<<<(BH * TD) / 256, 256>>>();
    k_ygemm<<<dim3(TD / 128, BH), 256>>>();
    k_outgemm<<<dim3(CD / 128, RWS / 128), 256>>>(out);
}